// round 7
// baseline (speedup 1.0000x reference)
#include <cuda_runtime.h>
#include <math.h>
#include <stdint.h>

#define NN 4096
#define KK 32
#define DD 256
#define HH 128
#define GG 384   // 3*H
#define SUBS 4   // CTAs per cluster-group

typedef unsigned long long ull;

// ---------------- scratch (__device__ globals, no allocation) ----------------
__device__ int    g_order[NN];
__device__ int    g_len[KK];
__device__ int    g_off[KK];
__device__ float4 g_Wih0T[(DD/4)*GG];
__device__ float  g_xw0[NN*GG];
__device__ float  g_cemb[KK*HH];
__device__ float  g_scores[NN];
__device__ unsigned g_ctr;

// ---------------- PTX helpers ------------------------------------------------
__device__ __forceinline__ uint32_t smem_u32(const void* p) {
    uint32_t a;
    asm("{ .reg .u64 t; cvta.to.shared.u64 t, %1; cvt.u32.u64 %0, t; }"
        : "=r"(a) : "l"(p));
    return a;
}
__device__ __forceinline__ void st_async_f32(uint32_t laddr, uint32_t lmbar,
                                             int rank, float v) {
    uint32_t ra, rb;
    asm volatile("mapa.shared::cluster.u32 %0, %1, %2;" : "=r"(ra) : "r"(laddr), "r"(rank));
    asm volatile("mapa.shared::cluster.u32 %0, %1, %2;" : "=r"(rb) : "r"(lmbar), "r"(rank));
    uint32_t b = __float_as_uint(v);
    asm volatile("st.async.shared::cluster.mbarrier::complete_tx::bytes.b32 [%0], %1, [%2];"
                 :: "r"(ra), "r"(b), "r"(rb) : "memory");
}
__device__ __forceinline__ void rearm_bar(uint32_t mbar, uint32_t txbytes) {
    asm volatile("mbarrier.arrive.expect_tx.shared::cta.b64 _, [%0], %1;"
                 :: "r"(mbar), "r"(txbytes) : "memory");
}
__device__ __forceinline__ void wait_bar(uint32_t mbar, uint32_t parity) {
    asm volatile(
        "{\n\t.reg .pred P;\n\t"
        "LW%=:\n\t"
        "mbarrier.try_wait.parity.acquire.cta.shared::cta.b64 P, [%0], %1;\n\t"
        "@!P bra LW%=;\n\t}"
        :: "r"(mbar), "r"(parity) : "memory");
}
__device__ __forceinline__ void fma2(ull& d, ull a, ull b) {
    asm("fma.rn.f32x2 %0, %1, %2, %0;" : "+l"(d) : "l"(a), "l"(b));
}
__device__ __forceinline__ float2 unpk(ull v) {
    float2 r;
    asm("mov.b64 {%0, %1}, %2;" : "=f"(r.x), "=f"(r.y) : "l"(v));
    return r;
}
__device__ __forceinline__ float tanha(float x) {
    float y;
    asm("tanh.approx.f32 %0, %1;" : "=f"(y) : "f"(x));
    return y;
}
__device__ __forceinline__ float siga(float x) {
    return fmaf(0.5f, tanha(0.5f * x), 0.5f);
}

// ---------------- K0: fused transpose (blocks 0..23) + order (block 24) -----
__global__ __launch_bounds__(1024) void k_prep(const float* __restrict__ W_ih0,
                                               const int* __restrict__ labels) {
    if (blockIdx.x < 24) {
        int idx = blockIdx.x * 1024 + threadIdx.x;
        int k4 = idx & 63;
        int g  = idx >> 6;
        float4 v = *reinterpret_cast<const float4*>(W_ih0 + g * DD + 4 * k4);
        g_Wih0T[k4 * GG + g] = v;
        return;
    }
    __shared__ int slab[NN];
    __shared__ int s_len[KK];
    __shared__ int s_off[KK];
    int tid = threadIdx.x;
    int c    = tid >> 5;
    int lane = tid & 31;
    if (tid == 0) g_ctr = 0;   // reset last-block counter each launch/replay

#pragma unroll
    for (int r = 0; r < NN / 1024; r++)
        slab[r * 1024 + tid] = labels[r * 1024 + tid];
    __syncthreads();

    int count = 0;
    for (int base = 0; base < NN; base += 32) {
        int lab = slab[base + lane];
        unsigned m = __ballot_sync(0xffffffffu, lab == c);
        count += __popc(m);
    }
    if (lane == 0) s_len[c] = count;
    __syncthreads();

    if (c == 0) {
        int len = s_len[lane];
        int off = 0;
        for (int j = 0; j < KK; j++) {
            int lj = __shfl_sync(0xffffffffu, len, j);
            if (j < lane) off += lj;
        }
        s_off[lane] = off;
        g_len[lane] = len;
        g_off[lane] = off;
    }
    __syncthreads();

    int off = s_off[c];
    int cnt = 0;
    for (int base = 0; base < NN; base += 32) {
        int lab = slab[base + lane];
        unsigned m = __ballot_sync(0xffffffffu, lab == c);
        if (lab == c) {
            int p = cnt + __popc(m & ((1u << lane) - 1u));
            g_order[off + p] = base + lane;
        }
        cnt += __popc(m);
    }
}

// ---------------- K2: xw0 = X_gathered @ W_ih0^T + b_ih0 (f32x2) ------------
#define TS 16
__global__ __launch_bounds__(GG) void k_xw0(const float* __restrict__ x,
                                            const float* __restrict__ b_ih0) {
    __shared__ __align__(16) float shx[TS * DD];
    int g  = threadIdx.x;
    int s0 = blockIdx.x * TS;

    for (int idx = g; idx < TS * DD; idx += GG) {
        int s2 = idx / DD;
        int kk = idx % DD;
        int sent = g_order[s0 + s2];
        shx[idx] = x[sent * DD + kk];
    }
    __syncthreads();

    ull a01[TS], a23[TS];
#pragma unroll
    for (int i = 0; i < TS; i++) { a01[i] = 0ull; a23[i] = 0ull; }

    const ulonglong2* W2 = reinterpret_cast<const ulonglong2*>(g_Wih0T);
    for (int k4 = 0; k4 < DD / 4; k4++) {
        ulonglong2 w = W2[k4 * GG + g];
#pragma unroll
        for (int s2 = 0; s2 < TS; s2++) {
            ulonglong2 xv = *reinterpret_cast<const ulonglong2*>(&shx[s2 * DD + 4 * k4]);
            fma2(a01[s2], w.x, xv.x);
            fma2(a23[s2], w.y, xv.y);
        }
    }
    float b = b_ih0[g];
#pragma unroll
    for (int s2 = 0; s2 < TS; s2++) {
        float2 p = unpk(a01[s2]), q = unpk(a23[s2]);
        g_xw0[(s0 + s2) * GG + g] = (p.x + p.y) + (q.x + q.y) + b;
    }
}

// ---------------- K3: 2-layer GRU, 4-CTA group, TWO clusters interleaved -----
// Streams A and B alternate inside each superstep so each stream's DSMEM
// exchange flight is hidden under the other stream's matvec+gate work.
__global__ __launch_bounds__(GG, 1) __cluster_dims__(SUBS, 1, 1)
void k_gru(const float* __restrict__ W_hh0, const float* __restrict__ W_ih1,
           const float* __restrict__ W_hh1,
           const float* __restrict__ b_ih0, const float* __restrict__ b_hh0,
           const float* __restrict__ b_ih1, const float* __restrict__ b_hh1) {
    __shared__ __align__(16) float sh1A[2][HH], sh2A[2][HH];
    __shared__ __align__(16) float sh1B[2][HH], sh2B[2][HH];
    __shared__ float sp0A[GG], sp1A[GG];
    __shared__ float sp0B[GG], sp1B[GG];
    __shared__ __align__(8) unsigned long long mbar[4];  // A:0,1  B:2,3

    int t   = threadIdx.x;
    int sub = blockIdx.x & (SUBS - 1);
    int grp = blockIdx.x / SUBS;
    int cA  = grp * 2;
    int cB  = grp * 2 + 1;

    // layer-0 role: 4 threads per row, 96 rows
    int q0 = t / 96;
    int i0 = t % 96;
    int g0 = i0 >> 5, e0 = i0 & 31;
    int R0 = 128 * g0 + 32 * sub + e0;

    // layer-1 role: 2 threads per row, 192 rows (96 Wih1 + 96 Whh1)
    int half = t / 192;
    int i1   = t % 192;
    int isW  = (i1 >= 96);
    int r1   = isW ? (i1 - 96) : i1;
    int g1 = r1 >> 5, e1 = r1 & 31;
    int R1 = 128 * g1 + 32 * sub + e1;

    // ---- register-resident weights (shared by both streams) ----
    ulonglong2 w0[8];
    const ulonglong2* p0 = reinterpret_cast<const ulonglong2*>(W_hh0 + R0 * HH + 32 * q0);
#pragma unroll
    for (int j = 0; j < 8; j++) w0[j] = p0[j];

    ulonglong2 w1[16];
    const float* Wsrc = isW ? W_hh1 : W_ih1;
    const ulonglong2* p1 = reinterpret_cast<const ulonglong2*>(Wsrc + R1 * HH + 64 * half);
#pragma unroll
    for (int j = 0; j < 16; j++) w1[j] = p1[j];

    // ---- biases: warp0 = layer0 gates, warp1 = layer1 gates ----
    float br_i = 0, bz_i = 0, bn_i = 0, br_h = 0, bz_h = 0, bn_h = 0;
    if (t < 32) {
        int e = 32 * sub + t;
        br_i = b_ih0[e]; bz_i = b_ih0[e + 128]; bn_i = b_ih0[e + 256];
        br_h = b_hh0[e]; bz_h = b_hh0[e + 128]; bn_h = b_hh0[e + 256];
    } else if (t < 64) {
        int e = 32 * sub + (t - 32);
        br_i = b_ih1[e]; bz_i = b_ih1[e + 128]; bn_i = b_ih1[e + 256];
        br_h = b_hh1[e]; bz_h = b_hh1[e + 128]; bn_h = b_hh1[e + 256];
    }

    if (t < HH) {
        sh1A[0][t] = 0.f; sh1A[1][t] = 0.f; sh2A[0][t] = 0.f; sh2A[1][t] = 0.f;
        sh1B[0][t] = 0.f; sh1B[1][t] = 0.f; sh2B[0][t] = 0.f; sh2B[1][t] = 0.f;
    }

    uint32_t mbA[2], mbB[2];
    mbA[0] = smem_u32(&mbar[0]); mbA[1] = smem_u32(&mbar[1]);
    mbB[0] = smem_u32(&mbar[2]); mbB[1] = smem_u32(&mbar[3]);
    const uint32_t TX = 2 * HH * 4;  // per stream per phase
    if (t == 0) {
#pragma unroll
        for (int j = 0; j < 4; j++)
            asm volatile("mbarrier.init.shared.b64 [%0], 1;" :: "r"(mbA[0] + 8u * j) : "memory");
        rearm_bar(mbA[0], TX); rearm_bar(mbA[1], TX);
        rearm_bar(mbB[0], TX); rearm_bar(mbB[1], TX);
    }
    asm volatile("fence.proxy.async.shared::cta;" ::: "memory");
    __syncthreads();
    asm volatile("barrier.cluster.arrive.aligned;" ::: "memory");
    asm volatile("barrier.cluster.wait.aligned;" ::: "memory");

    int lenA = g_len[cA], offA = g_off[cA];
    int lenB = g_len[cB], offB = g_off[cB];
    int stepsA = lenA > 0 ? lenA : 1;
    int stepsB = lenB > 0 ? lenB : 1;
    int S = stepsA > stepsB ? stepsA : stepsB;

    uint32_t sh1Aa = smem_u32(&sh1A[0][0]);
    uint32_t sh2Aa = smem_u32(&sh2A[0][0]);
    uint32_t sh1Ba = smem_u32(&sh1B[0][0]);
    uint32_t sh2Ba = smem_u32(&sh2B[0][0]);

    float h2finA = 0.f, h2finB = 0.f;

    for (int s = 0; s <= S; s++) {
        int rb1 = (s + 1) & 1;   // h1[s-1]
        int wb1 = s & 1;         // h1[s]
        int rb2 = s & 1;         // h2[s-2]
        int wb2 = (s + 1) & 1;   // h2[s-1]
        uint32_t parW = (uint32_t)(((s - 1) >> 1) & 1);

        // ================= stream A =================
        {
            float xwr = br_i, xwz = bz_i, xwn = bn_i;
            if (t < 32 && s < lenA) {
                const float* xp = g_xw0 + (offA + s) * GG + 32 * sub + t;
                xwr = xp[0]; xwz = xp[128]; xwn = xp[256];
            }
            if (s > 0) {
                wait_bar(mbA[(s - 1) & 1], parW);
                if (t == 0) rearm_bar(mbA[(s - 1) & 1], TX);
            }
            {
                ull a01 = 0ull, a23 = 0ull;
                const ulonglong2* hv = reinterpret_cast<const ulonglong2*>(&sh1A[rb1][32 * q0]);
#pragma unroll
                for (int j = 0; j < 8; j++) {
                    ulonglong2 h = hv[j];
                    fma2(a01, w0[j].x, h.x);
                    fma2(a23, w0[j].y, h.y);
                }
                float2 p = unpk(a01), q = unpk(a23);
                sp0A[t] = (p.x + p.y) + (q.x + q.y);
            }
            {
                const ulonglong2* hv = isW
                    ? reinterpret_cast<const ulonglong2*>(&sh2A[rb2][64 * half])
                    : reinterpret_cast<const ulonglong2*>(&sh1A[rb1][64 * half]);
                ull a01 = 0ull, a23 = 0ull;
#pragma unroll
                for (int j = 0; j < 16; j++) {
                    ulonglong2 h = hv[j];
                    fma2(a01, w1[j].x, h.x);
                    fma2(a23, w1[j].y, h.y);
                }
                float2 p = unpk(a01), q = unpk(a23);
                sp1A[t] = (p.x + p.y) + (q.x + q.y);
            }
            __syncthreads();

            if (t < 32) {
                float hr = sp0A[t]      + sp0A[96 + t]  + sp0A[192 + t] + sp0A[288 + t] + br_h;
                float hz = sp0A[32 + t] + sp0A[128 + t] + sp0A[224 + t] + sp0A[320 + t] + bz_h;
                float hn = sp0A[64 + t] + sp0A[160 + t] + sp0A[256 + t] + sp0A[352 + t] + bn_h;
                float rg = siga(xwr + hr);
                float zg = siga(xwz + hz);
                float ng = tanha(xwn + rg * hn);
                float h1o = sh1A[rb1][32 * sub + t];
                float h1n = (1.f - zg) * ng + zg * h1o;
                uint32_t loff = sh1Aa + (uint32_t)(wb1 * HH + 32 * sub + t) * 4u;
#pragma unroll
                for (int p = 0; p < SUBS; p++)
                    st_async_f32(loff, mbA[s & 1], p, h1n);
            } else if (t < 64) {
                int e = t - 32;
                float xr = sp1A[e]       + sp1A[192 + e] + br_i;
                float xz = sp1A[32 + e]  + sp1A[224 + e] + bz_i;
                float xn = sp1A[64 + e]  + sp1A[256 + e] + bn_i;
                float hr = sp1A[96 + e]  + sp1A[288 + e] + br_h;
                float hz = sp1A[128 + e] + sp1A[320 + e] + bz_h;
                float hn = sp1A[160 + e] + sp1A[352 + e] + bn_h;
                float rg = siga(xr + hr);
                float zg = siga(xz + hz);
                float ng = tanha(xn + rg * hn);
                float h2o = sh2A[rb2][32 * sub + e];
                float h2n = (1.f - zg) * ng + zg * h2o;
                if (s == 0) h2n = 0.f;
                if (s == stepsA) h2finA = h2n;
                uint32_t loff = sh2Aa + (uint32_t)(wb2 * HH + 32 * sub + e) * 4u;
#pragma unroll
                for (int p = 0; p < SUBS; p++)
                    st_async_f32(loff, mbA[s & 1], p, h2n);
            }
        }

        // ================= stream B =================
        {
            float xwr = br_i, xwz = bz_i, xwn = bn_i;
            if (t < 32 && s < lenB) {
                const float* xp = g_xw0 + (offB + s) * GG + 32 * sub + t;
                xwr = xp[0]; xwz = xp[128]; xwn = xp[256];
            }
            if (s > 0) {
                wait_bar(mbB[(s - 1) & 1], parW);
                if (t == 0) rearm_bar(mbB[(s - 1) & 1], TX);
            }
            {
                ull a01 = 0ull, a23 = 0ull;
                const ulonglong2* hv = reinterpret_cast<const ulonglong2*>(&sh1B[rb1][32 * q0]);
#pragma unroll
                for (int j = 0; j < 8; j++) {
                    ulonglong2 h = hv[j];
                    fma2(a01, w0[j].x, h.x);
                    fma2(a23, w0[j].y, h.y);
                }
                float2 p = unpk(a01), q = unpk(a23);
                sp0B[t] = (p.x + p.y) + (q.x + q.y);
            }
            {
                const ulonglong2* hv = isW
                    ? reinterpret_cast<const ulonglong2*>(&sh2B[rb2][64 * half])
                    : reinterpret_cast<const ulonglong2*>(&sh1B[rb1][64 * half]);
                ull a01 = 0ull, a23 = 0ull;
#pragma unroll
                for (int j = 0; j < 16; j++) {
                    ulonglong2 h = hv[j];
                    fma2(a01, w1[j].x, h.x);
                    fma2(a23, w1[j].y, h.y);
                }
                float2 p = unpk(a01), q = unpk(a23);
                sp1B[t] = (p.x + p.y) + (q.x + q.y);
            }
            __syncthreads();

            if (t < 32) {
                float hr = sp0B[t]      + sp0B[96 + t]  + sp0B[192 + t] + sp0B[288 + t] + br_h;
                float hz = sp0B[32 + t] + sp0B[128 + t] + sp0B[224 + t] + sp0B[320 + t] + bz_h;
                float hn = sp0B[64 + t] + sp0B[160 + t] + sp0B[256 + t] + sp0B[352 + t] + bn_h;
                float rg = siga(xwr + hr);
                float zg = siga(xwz + hz);
                float ng = tanha(xwn + rg * hn);
                float h1o = sh1B[rb1][32 * sub + t];
                float h1n = (1.f - zg) * ng + zg * h1o;
                uint32_t loff = sh1Ba + (uint32_t)(wb1 * HH + 32 * sub + t) * 4u;
#pragma unroll
                for (int p = 0; p < SUBS; p++)
                    st_async_f32(loff, mbB[s & 1], p, h1n);
            } else if (t < 64) {
                int e = t - 32;
                float xr = sp1B[e]       + sp1B[192 + e] + br_i;
                float xz = sp1B[32 + e]  + sp1B[224 + e] + bz_i;
                float xn = sp1B[64 + e]  + sp1B[256 + e] + bn_i;
                float hr = sp1B[96 + e]  + sp1B[288 + e] + br_h;
                float hz = sp1B[128 + e] + sp1B[320 + e] + bz_h;
                float hn = sp1B[160 + e] + sp1B[352 + e] + bn_h;
                float rg = siga(xr + hr);
                float zg = siga(xz + hz);
                float ng = tanha(xn + rg * hn);
                float h2o = sh2B[rb2][32 * sub + e];
                float h2n = (1.f - zg) * ng + zg * h2o;
                if (s == 0) h2n = 0.f;
                if (s == stepsB) h2finB = h2n;
                uint32_t loff = sh2Ba + (uint32_t)(wb2 * HH + 32 * sub + e) * 4u;
#pragma unroll
                for (int p = 0; p < SUBS; p++)
                    st_async_f32(loff, mbB[s & 1], p, h2n);
            }
        }
    }

    // drain final exchanges
    wait_bar(mbA[S & 1], (uint32_t)((S >> 1) & 1));
    wait_bar(mbB[S & 1], (uint32_t)((S >> 1) & 1));

    if (t >= 32 && t < 64) {
        g_cemb[cA * HH + 32 * sub + (t - 32)] = h2finA;
        g_cemb[cB * HH + 32 * sub + (t - 32)] = h2finB;
    }

    asm volatile("barrier.cluster.arrive.aligned;" ::: "memory");
    asm volatile("barrier.cluster.wait.aligned;" ::: "memory");
}

// ---------------- K4: scores + (last block) segment-sum + combine ------------
__global__ __launch_bounds__(512) void k_score(const float* __restrict__ x,
                                               const int* __restrict__ labels,
                                               const float* __restrict__ lin_v,
                                               const float* __restrict__ lin_g,
                                               const float* __restrict__ lin_b,
                                               float* __restrict__ out) {
    __shared__ float swn[GG];
    __shared__ float red[16];
    __shared__ float scs[KK];
    __shared__ int   s_last;
    int t = threadIdx.x;
    int warp = t >> 5, lane = t & 31;

    // ---- weight-norm (redundant per block) ----
    float v = (t < GG) ? lin_v[t] : 0.f;
    float sq = v * v;
    for (int o = 16; o > 0; o >>= 1) sq += __shfl_xor_sync(0xffffffffu, sq, o);
    if (lane == 0) red[warp] = sq;
    __syncthreads();
    if (t == 0) {
        float s = 0.f;
#pragma unroll
        for (int i = 0; i < 16; i++) s += red[i];
        red[0] = 1.f / sqrtf(s);
    }
    __syncthreads();
    if (t < GG) swn[t] = lin_g[0] * v * red[0];
    __syncthreads();

    // ---- per-cluster scores ----
#pragma unroll
    for (int j = 0; j < 2; j++) {
        int c = warp * 2 + j;
        float s = 0.f;
#pragma unroll
        for (int q = 0; q < HH / 32; q++)
            s += g_cemb[c * HH + q * 32 + lane] * swn[DD + q * 32 + lane];
        for (int o = 16; o > 0; o >>= 1) s += __shfl_xor_sync(0xffffffffu, s, o);
        if (lane == 0) scs[c] = s;
    }
    __syncthreads();

    // ---- sentence scores: one warp per sentence ----
    int i = blockIdx.x * 16 + warp;
    const float* xr = x + i * DD;
    float s = 0.f;
#pragma unroll
    for (int q = 0; q < DD / 32; q++)
        s += xr[q * 32 + lane] * swn[q * 32 + lane];
    for (int o = 16; o > 0; o >>= 1) s += __shfl_xor_sync(0xffffffffu, s, o);
    if (lane == 0)
        g_scores[i] = tanhf(s + scs[labels[i]] + lin_b[0]);

    // ---- last block does the tail ----
    __threadfence();
    __syncthreads();
    if (t == 0) {
        unsigned done = atomicAdd(&g_ctr, 1u);
        s_last = (done == gridDim.x - 1) ? 1 : 0;
    }
    __syncthreads();
    if (!s_last) return;
    __threadfence();

    __shared__ float s_sum[KK];
    __shared__ int   slab2[NN];
    __shared__ float ssc2[NN];
#pragma unroll
    for (int r = 0; r < NN / 512; r++) {
        slab2[r * 512 + t] = labels[r * 512 + t];
        ssc2[r * 512 + t]  = g_scores[r * 512 + t];
    }
    __syncthreads();

    // 16 warps, 2 clusters each
#pragma unroll
    for (int j = 0; j < 2; j++) {
        int c = warp * 2 + j;
        float acc = 0.f;
        for (int base = 0; base < NN; base += 32) {
            int lab = slab2[base + lane];
            float vv = ssc2[base + lane];
            if (lab == c) acc += vv;
        }
        for (int o = 16; o > 0; o >>= 1) acc += __shfl_xor_sync(0xffffffffu, acc, o);
        if (lane == 0) s_sum[c] = acc;
    }
    __syncthreads();

#pragma unroll
    for (int r = 0; r < NN / 512; r++) {
        int i2 = r * 512 + t;
        float sal = ssc2[i2] / s_sum[slab2[i2]];
        float p = fmaxf(0.5f, expf(-(float)(i2 + 1) * 0.0625f));  // 1/4096^(1/3)=1/16
        out[i2] = 0.5f * sal + 0.5f * p;
    }
}

// ---------------- launch ------------------------------------------------------
extern "C" void kernel_launch(void* const* d_in, const int* in_sizes, int n_in,
                              void* d_out, int out_size) {
    const float* x     = (const float*)d_in[0];
    const int*   labels= (const int*)  d_in[1];
    const float* W_ih0 = (const float*)d_in[2];
    const float* W_hh0 = (const float*)d_in[3];
    const float* b_ih0 = (const float*)d_in[4];
    const float* b_hh0 = (const float*)d_in[5];
    const float* W_ih1 = (const float*)d_in[6];
    const float* W_hh1 = (const float*)d_in[7];
    const float* b_ih1 = (const float*)d_in[8];
    const float* b_hh1 = (const float*)d_in[9];
    const float* lin_v = (const float*)d_in[10];
    const float* lin_g = (const float*)d_in[11];
    const float* lin_b = (const float*)d_in[12];
    float* out = (float*)d_out;

    k_prep<<<25, 1024>>>(W_ih0, labels);
    k_xw0<<<NN / TS, GG>>>(x, b_ih0);
    k_gru<<<(KK / 2) * SUBS, GG>>>(W_hh0, W_ih1, W_hh1, b_ih0, b_hh0, b_ih1, b_hh1);
    k_score<<<NN / 16, 512>>>(x, labels, lin_v, lin_g, lin_b, out);
}

// round 8
// speedup vs baseline: 1.4152x; 1.4152x over previous
#include <cuda_runtime.h>
#include <math.h>
#include <stdint.h>

#define NN 4096
#define KK 32
#define DD 256
#define HH 128
#define GG 384   // 3*H
#define SUBS 4   // CTAs per cluster-sequence

typedef unsigned long long ull;

// ---------------- scratch (__device__ globals, no allocation) ----------------
__device__ int    g_order[NN];
__device__ int    g_len[KK];
__device__ int    g_off[KK];
__device__ float4 g_Wih0T[(DD/4)*GG];
__device__ float  g_xw0[NN*GG];
__device__ float  g_cemb[KK*HH];
__device__ float  g_scores[NN];

// ---------------- PTX helpers ------------------------------------------------
__device__ __forceinline__ uint32_t smem_u32(const void* p) {
    uint32_t a;
    asm("{ .reg .u64 t; cvta.to.shared.u64 t, %1; cvt.u32.u64 %0, t; }"
        : "=r"(a) : "l"(p));
    return a;
}
__device__ __forceinline__ uint32_t mapa_rank(uint32_t laddr, int rank) {
    uint32_t r;
    asm("mapa.shared::cluster.u32 %0, %1, %2;" : "=r"(r) : "r"(laddr), "r"(rank));
    return r;
}
// remote store + barrier tx-completion with PRE-MAPPED addresses
__device__ __forceinline__ void st_async_pre(uint32_t raddr, uint32_t rmbar, float v) {
    uint32_t b = __float_as_uint(v);
    asm volatile("st.async.shared::cluster.mbarrier::complete_tx::bytes.b32 [%0], %1, [%2];"
                 :: "r"(raddr), "r"(b), "r"(rmbar) : "memory");
}
__device__ __forceinline__ void rearm_bar(uint32_t mbar, uint32_t txbytes) {
    asm volatile("mbarrier.arrive.expect_tx.shared::cta.b64 _, [%0], %1;"
                 :: "r"(mbar), "r"(txbytes) : "memory");
}
__device__ __forceinline__ void wait_bar(uint32_t mbar, uint32_t parity) {
    asm volatile(
        "{\n\t.reg .pred P;\n\t"
        "LW%=:\n\t"
        "mbarrier.try_wait.parity.acquire.cta.shared::cta.b64 P, [%0], %1;\n\t"
        "@!P bra LW%=;\n\t}"
        :: "r"(mbar), "r"(parity) : "memory");
}
__device__ __forceinline__ void fma2(ull& d, ull a, ull b) {
    asm("fma.rn.f32x2 %0, %1, %2, %0;" : "+l"(d) : "l"(a), "l"(b));
}
__device__ __forceinline__ float2 unpk(ull v) {
    float2 r;
    asm("mov.b64 {%0, %1}, %2;" : "=f"(r.x), "=f"(r.y) : "l"(v));
    return r;
}
__device__ __forceinline__ float tanha(float x) {
    float y;
    asm("tanh.approx.f32 %0, %1;" : "=f"(y) : "f"(x));
    return y;
}
__device__ __forceinline__ float siga(float x) {
    return fmaf(0.5f, tanha(0.5f * x), 0.5f);
}

// ---------------- K0: fused transpose (blocks 0..23) + order (block 24) -----
__global__ __launch_bounds__(1024) void k_prep(const float* __restrict__ W_ih0,
                                               const int* __restrict__ labels) {
    if (blockIdx.x < 24) {
        int idx = blockIdx.x * 1024 + threadIdx.x;
        int k4 = idx & 63;
        int g  = idx >> 6;
        float4 v = *reinterpret_cast<const float4*>(W_ih0 + g * DD + 4 * k4);
        g_Wih0T[k4 * GG + g] = v;
        return;
    }
    __shared__ int slab[NN];
    __shared__ int s_len[KK];
    __shared__ int s_off[KK];
    int tid = threadIdx.x;
    int c    = tid >> 5;
    int lane = tid & 31;

#pragma unroll
    for (int r = 0; r < NN / 1024; r++)
        slab[r * 1024 + tid] = labels[r * 1024 + tid];
    __syncthreads();

    int count = 0;
    for (int base = 0; base < NN; base += 32) {
        int lab = slab[base + lane];
        unsigned m = __ballot_sync(0xffffffffu, lab == c);
        count += __popc(m);
    }
    if (lane == 0) s_len[c] = count;
    __syncthreads();

    if (c == 0) {
        int len = s_len[lane];
        int off = 0;
        for (int j = 0; j < KK; j++) {
            int lj = __shfl_sync(0xffffffffu, len, j);
            if (j < lane) off += lj;
        }
        s_off[lane] = off;
        g_len[lane] = len;
        g_off[lane] = off;
    }
    __syncthreads();

    int off = s_off[c];
    int cnt = 0;
    for (int base = 0; base < NN; base += 32) {
        int lab = slab[base + lane];
        unsigned m = __ballot_sync(0xffffffffu, lab == c);
        if (lab == c) {
            int p = cnt + __popc(m & ((1u << lane) - 1u));
            g_order[off + p] = base + lane;
        }
        cnt += __popc(m);
    }
}

// ---------------- K2: xw0 = X_gathered @ W_ih0^T + b_ih0 (f32x2) ------------
#define TS 16
__global__ __launch_bounds__(GG) void k_xw0(const float* __restrict__ x,
                                            const float* __restrict__ b_ih0) {
    __shared__ __align__(16) float shx[TS * DD];
    int g  = threadIdx.x;
    int s0 = blockIdx.x * TS;

    for (int idx = g; idx < TS * DD; idx += GG) {
        int s2 = idx / DD;
        int kk = idx % DD;
        int sent = g_order[s0 + s2];
        shx[idx] = x[sent * DD + kk];
    }
    __syncthreads();

    ull a01[TS], a23[TS];
#pragma unroll
    for (int i = 0; i < TS; i++) { a01[i] = 0ull; a23[i] = 0ull; }

    const ulonglong2* W2 = reinterpret_cast<const ulonglong2*>(g_Wih0T);
    for (int k4 = 0; k4 < DD / 4; k4++) {
        ulonglong2 w = W2[k4 * GG + g];
#pragma unroll
        for (int s2 = 0; s2 < TS; s2++) {
            ulonglong2 xv = *reinterpret_cast<const ulonglong2*>(&shx[s2 * DD + 4 * k4]);
            fma2(a01[s2], w.x, xv.x);
            fma2(a23[s2], w.y, xv.y);
        }
    }
    float b = b_ih0[g];
#pragma unroll
    for (int s2 = 0; s2 < TS; s2++) {
        float2 p = unpk(a01[s2]), q = unpk(a23[s2]);
        g_xw0[(s0 + s2) * GG + g] = (p.x + p.y) + (q.x + q.y) + b;
    }
}

// ---------------- K3: 2-layer GRU, 4-CTA cluster, pipelined layers -----------
// Producer warps (2..11) use bar.arrive; gate warps (0,1) bar.sync. Remote
// DSMEM/mbarrier addresses pre-mapped outside the loop.
__global__ __launch_bounds__(GG, 1) __cluster_dims__(SUBS, 1, 1)
void k_gru(const float* __restrict__ W_hh0, const float* __restrict__ W_ih1,
           const float* __restrict__ W_hh1,
           const float* __restrict__ b_ih0, const float* __restrict__ b_hh0,
           const float* __restrict__ b_ih1, const float* __restrict__ b_hh1) {
    __shared__ __align__(16) float sh1[2][HH];
    __shared__ __align__(16) float sh2[2][HH];
    __shared__ float sp0[GG];
    __shared__ float sp1[GG];
    __shared__ __align__(8) unsigned long long mbar[2];

    int t   = threadIdx.x;
    int sub = blockIdx.x & (SUBS - 1);
    int c   = blockIdx.x / SUBS;

    // layer-0 role: 4 threads per row, 96 rows
    int q0 = t / 96;
    int i0 = t % 96;
    int g0 = i0 >> 5, e0 = i0 & 31;
    int R0 = 128 * g0 + 32 * sub + e0;

    // layer-1 role: 2 threads per row, 192 rows (96 Wih1 + 96 Whh1)
    int half = t / 192;
    int i1   = t % 192;
    int isW  = (i1 >= 96);
    int r1   = isW ? (i1 - 96) : i1;
    int g1 = r1 >> 5, e1 = r1 & 31;
    int R1 = 128 * g1 + 32 * sub + e1;

    // ---- register-resident weights (f32x2 pairs) ----
    ulonglong2 w0[8];
    const ulonglong2* p0 = reinterpret_cast<const ulonglong2*>(W_hh0 + R0 * HH + 32 * q0);
#pragma unroll
    for (int j = 0; j < 8; j++) w0[j] = p0[j];

    ulonglong2 w1[16];
    const float* Wsrc = isW ? W_hh1 : W_ih1;
    const ulonglong2* p1 = reinterpret_cast<const ulonglong2*>(Wsrc + R1 * HH + 64 * half);
#pragma unroll
    for (int j = 0; j < 16; j++) w1[j] = p1[j];

    // ---- biases: warp0 = layer0 gates, warp1 = layer1 gates ----
    float br_i = 0, bz_i = 0, bn_i = 0, br_h = 0, bz_h = 0, bn_h = 0;
    if (t < 32) {
        int e = 32 * sub + t;
        br_i = b_ih0[e]; bz_i = b_ih0[e + 128]; bn_i = b_ih0[e + 256];
        br_h = b_hh0[e]; bz_h = b_hh0[e + 128]; bn_h = b_hh0[e + 256];
    } else if (t < 64) {
        int e = 32 * sub + (t - 32);
        br_i = b_ih1[e]; bz_i = b_ih1[e + 128]; bn_i = b_ih1[e + 256];
        br_h = b_hh1[e]; bz_h = b_hh1[e + 128]; bn_h = b_hh1[e + 256];
    }

    if (t < HH) { sh1[0][t] = 0.f; sh1[1][t] = 0.f; sh2[0][t] = 0.f; sh2[1][t] = 0.f; }

    uint32_t mb[2];
    mb[0] = smem_u32(&mbar[0]); mb[1] = smem_u32(&mbar[1]);
    const uint32_t TX = 2 * HH * 4;  // 128 h1 + 128 h2 floats per phase
    if (t == 0) {
        asm volatile("mbarrier.init.shared.b64 [%0], 1;" :: "r"(mb[0]) : "memory");
        asm volatile("mbarrier.init.shared.b64 [%0], 1;" :: "r"(mb[1]) : "memory");
        rearm_bar(mb[0], TX); rearm_bar(mb[1], TX);
    }
    asm volatile("fence.proxy.async.shared::cta;" ::: "memory");
    __syncthreads();
    asm volatile("barrier.cluster.arrive.aligned;" ::: "memory");
    asm volatile("barrier.cluster.wait.aligned;" ::: "memory");

    int len   = g_len[c];
    int off   = g_off[c];
    int steps = len > 0 ? len : 1;

    uint32_t sh1a = smem_u32(&sh1[0][0]);
    uint32_t sh2a = smem_u32(&sh2[0][0]);

    // ---- pre-mapped remote bases (gate warps only use them) ----
    uint32_t r_sh1[SUBS], r_sh2[SUBS], r_mb[SUBS];
#pragma unroll
    for (int p = 0; p < SUBS; p++) {
        r_sh1[p] = mapa_rank(sh1a, p);
        r_sh2[p] = mapa_rank(sh2a, p);
        r_mb[p]  = mapa_rank(mb[0], p);
    }

    float h2fin = 0.f;

    for (int s = 0; s <= steps; s++) {
        int rb1 = (s + 1) & 1;   // h1[s-1]
        int wb1 = s & 1;         // h1[s]
        int rb2 = s & 1;         // h2[s-2]
        int wb2 = (s + 1) & 1;   // h2[s-1]
        uint32_t mboff = (uint32_t)((s & 1) * 8);

        // prefetch input gates BEFORE the wait (overlaps L2 latency)
        float xwr = br_i, xwz = bz_i, xwn = bn_i;
        if (t < 32 && s < len) {
            const float* xp = g_xw0 + (off + s) * GG + 32 * sub + t;
            xwr = xp[0]; xwz = xp[128]; xwn = xp[256];
        }

        if (s > 0) {
            wait_bar(mb[(s - 1) & 1], (uint32_t)(((s - 1) >> 1) & 1));
            if (t == 0) rearm_bar(mb[(s - 1) & 1], TX);  // arm iter s+1
        }

        // ---- layer 0 matvec over h1[s-1] (f32x2) ----
        {
            ull a01 = 0ull, a23 = 0ull;
            const ulonglong2* hv = reinterpret_cast<const ulonglong2*>(&sh1[rb1][32 * q0]);
#pragma unroll
            for (int j = 0; j < 8; j++) {
                ulonglong2 h = hv[j];
                fma2(a01, w0[j].x, h.x);
                fma2(a23, w0[j].y, h.y);
            }
            float2 p = unpk(a01), q = unpk(a23);
            sp0[t] = (p.x + p.y) + (q.x + q.y);
        }
        // ---- layer 1 matvecs over h1[s-1] / h2[s-2] (f32x2) ----
        {
            const ulonglong2* hv = isW
                ? reinterpret_cast<const ulonglong2*>(&sh2[rb2][64 * half])
                : reinterpret_cast<const ulonglong2*>(&sh1[rb1][64 * half]);
            ull a01 = 0ull, a23 = 0ull;
#pragma unroll
            for (int j = 0; j < 16; j++) {
                ulonglong2 h = hv[j];
                fma2(a01, w1[j].x, h.x);
                fma2(a23, w1[j].y, h.y);
            }
            float2 p = unpk(a01), q = unpk(a23);
            sp1[t] = (p.x + p.y) + (q.x + q.y);
        }

        if (t >= 64) {
            // producers: post arrival, run ahead to next iteration's wait
            asm volatile("bar.arrive 1, 384;" ::: "memory");
            continue;
        }
        // consumers (gate warps): wait for all sp writes
        asm volatile("bar.sync 1, 384;" ::: "memory");

        if (t < 32) {
            float hr = sp0[t]      + sp0[96 + t]  + sp0[192 + t] + sp0[288 + t] + br_h;
            float hz = sp0[32 + t] + sp0[128 + t] + sp0[224 + t] + sp0[320 + t] + bz_h;
            float hn = sp0[64 + t] + sp0[160 + t] + sp0[256 + t] + sp0[352 + t] + bn_h;
            float rg = siga(xwr + hr);
            float zg = siga(xwz + hz);
            float ng = tanha(xwn + rg * hn);
            float h1o = sh1[rb1][32 * sub + t];
            float h1n = (1.f - zg) * ng + zg * h1o;
            uint32_t woff = (uint32_t)(wb1 * HH + 32 * sub + t) * 4u;
#pragma unroll
            for (int p = 0; p < SUBS; p++)
                st_async_pre(r_sh1[p] + woff, r_mb[p] + mboff, h1n);
        } else {
            int e = t - 32;
            float xr = sp1[e]       + sp1[192 + e] + br_i;
            float xz = sp1[32 + e]  + sp1[224 + e] + bz_i;
            float xn = sp1[64 + e]  + sp1[256 + e] + bn_i;
            float hr = sp1[96 + e]  + sp1[288 + e] + br_h;
            float hz = sp1[128 + e] + sp1[320 + e] + bz_h;
            float hn = sp1[160 + e] + sp1[352 + e] + bn_h;
            float rg = siga(xr + hr);
            float zg = siga(xz + hz);
            float ng = tanha(xn + rg * hn);
            float h2o = sh2[rb2][32 * sub + e];
            float h2n = (1.f - zg) * ng + zg * h2o;
            if (s == 0) h2n = 0.f;        // h2[-1] = initial state
            if (s == steps) h2fin = h2n;  // h2[steps-1] = final
            uint32_t woff = (uint32_t)(wb2 * HH + 32 * sub + e) * 4u;
#pragma unroll
            for (int p = 0; p < SUBS; p++)
                st_async_pre(r_sh2[p] + woff, r_mb[p] + mboff, h2n);
        }
    }

    // drain final exchange so no st.async is in flight at exit
    wait_bar(mb[steps & 1], (uint32_t)((steps >> 1) & 1));

    if (t >= 32 && t < 64) g_cemb[c * HH + 32 * sub + (t - 32)] = h2fin;

    asm volatile("barrier.cluster.arrive.aligned;" ::: "memory");
    asm volatile("barrier.cluster.wait.aligned;" ::: "memory");
}

// ---------------- K4: per-sentence scores (wn + cscore computed in-block) ----
__global__ __launch_bounds__(512) void k_score(const float* __restrict__ x,
                                               const int* __restrict__ labels,
                                               const float* __restrict__ lin_v,
                                               const float* __restrict__ lin_g,
                                               const float* __restrict__ lin_b) {
    __shared__ float swn[GG];
    __shared__ float red[16];
    __shared__ float scs[KK];
    int t = threadIdx.x;
    int warp = t >> 5, lane = t & 31;

    float v = (t < GG) ? lin_v[t] : 0.f;
    float sq = v * v;
    for (int o = 16; o > 0; o >>= 1) sq += __shfl_xor_sync(0xffffffffu, sq, o);
    if (lane == 0) red[warp] = sq;
    __syncthreads();
    if (t == 0) {
        float s = 0.f;
#pragma unroll
        for (int i = 0; i < 16; i++) s += red[i];
        red[0] = 1.f / sqrtf(s);
    }
    __syncthreads();
    if (t < GG) swn[t] = lin_g[0] * v * red[0];
    __syncthreads();

#pragma unroll
    for (int j = 0; j < 2; j++) {
        int c = warp * 2 + j;
        float s = 0.f;
#pragma unroll
        for (int q = 0; q < HH / 32; q++)
            s += g_cemb[c * HH + q * 32 + lane] * swn[DD + q * 32 + lane];
        for (int o = 16; o > 0; o >>= 1) s += __shfl_xor_sync(0xffffffffu, s, o);
        if (lane == 0) scs[c] = s;
    }
    __syncthreads();

    int i = blockIdx.x * 16 + warp;
    const float* xr = x + i * DD;
    float s = 0.f;
#pragma unroll
    for (int q = 0; q < DD / 32; q++)
        s += xr[q * 32 + lane] * swn[q * 32 + lane];
    for (int o = 16; o > 0; o >>= 1) s += __shfl_xor_sync(0xffffffffu, s, o);
    if (lane == 0)
        g_scores[i] = tanhf(s + scs[labels[i]] + lin_b[0]);
}

// ---------------- K5: segment sum + final combine ----------------------------
__global__ void k_tail(const int* __restrict__ labels, float* __restrict__ out) {
    __shared__ float s_sum[KK];
    __shared__ int   slab[NN];
    __shared__ float ssc[NN];
    int tid = threadIdx.x;
#pragma unroll
    for (int r = 0; r < NN / 1024; r++) {
        slab[r * 1024 + tid] = labels[r * 1024 + tid];
        ssc[r * 1024 + tid]  = g_scores[r * 1024 + tid];
    }
    __syncthreads();

    int c = tid >> 5, lane = tid & 31;
    float s = 0.f;
    for (int base = 0; base < NN; base += 32) {
        int lab = slab[base + lane];
        float v = ssc[base + lane];
        if (lab == c) s += v;
    }
    for (int o = 16; o > 0; o >>= 1) s += __shfl_xor_sync(0xffffffffu, s, o);
    if (lane == 0) s_sum[c] = s;
    __syncthreads();

#pragma unroll
    for (int r = 0; r < NN / 1024; r++) {
        int i = r * 1024 + tid;
        float sal = ssc[i] / s_sum[slab[i]];
        float p = fmaxf(0.5f, expf(-(float)(i + 1) * 0.0625f));  // 1/4096^(1/3)=1/16
        out[i] = 0.5f * sal + 0.5f * p;
    }
}

// ---------------- launch ------------------------------------------------------
extern "C" void kernel_launch(void* const* d_in, const int* in_sizes, int n_in,
                              void* d_out, int out_size) {
    const float* x     = (const float*)d_in[0];
    const int*   labels= (const int*)  d_in[1];
    const float* W_ih0 = (const float*)d_in[2];
    const float* W_hh0 = (const float*)d_in[3];
    const float* b_ih0 = (const float*)d_in[4];
    const float* b_hh0 = (const float*)d_in[5];
    const float* W_ih1 = (const float*)d_in[6];
    const float* W_hh1 = (const float*)d_in[7];
    const float* b_ih1 = (const float*)d_in[8];
    const float* b_hh1 = (const float*)d_in[9];
    const float* lin_v = (const float*)d_in[10];
    const float* lin_g = (const float*)d_in[11];
    const float* lin_b = (const float*)d_in[12];
    float* out = (float*)d_out;

    k_prep<<<25, 1024>>>(W_ih0, labels);
    k_xw0<<<NN / TS, GG>>>(x, b_ih0);
    k_gru<<<KK * SUBS, GG>>>(W_hh0, W_ih1, W_hh1, b_ih0, b_hh0, b_ih1, b_hh1);
    k_score<<<NN / 16, 512>>>(x, labels, lin_v, lin_g, lin_b);
    k_tail<<<1, 1024>>>(labels, out);
}